// round 7
// baseline (speedup 1.0000x reference)
#include <cuda_runtime.h>

#define TPB 256
#define CPB 128                      // cells per tile
#define MAX_GRID 8192
#define TILE_F4 ((CPB * 30) / 4)     // 960 float4 per tile
#define TILE_FLOATS (CPB * 30)       // 3840 floats per tile

// SoA per-block partials: [k * grid + bid]
__device__ float g_partials[5 * MAX_GRID];
__device__ unsigned int g_counter = 0;   // atomicInc wraps -> replay-safe

__device__ __forceinline__ void cp_async16(unsigned int saddr, const void* gptr) {
    asm volatile("cp.async.cg.shared.global [%0], [%1], 16;" :: "r"(saddr), "l"(gptr));
}
__device__ __forceinline__ void cp_commit() {
    asm volatile("cp.async.commit_group;" ::: "memory");
}
__device__ __forceinline__ void cp_wait1() {
    asm volatile("cp.async.wait_group 1;" ::: "memory");
}

__device__ __forceinline__ float load_obj(const void* objmap, int idx, int flag) {
    if (flag == 2) return ((const float*)objmap)[idx];
    if (flag == 1) return (((const int*)objmap)[idx] != 0) ? 1.0f : 0.0f;
    return ((const unsigned char*)objmap)[idx] ? 1.0f : 0.0f;
}

__device__ __forceinline__ float iou_pred_vs_tgt(
    float px, float py, float pw, float ph,
    float tx1, float ty1, float tx2, float ty2, float tarea)
{
    const float invS = 1.0f / 14.0f;
    float cx = px * invS, cy = py * invS;
    float x1 = cx - 0.5f * pw, y1 = cy - 0.5f * ph;
    float x2 = cx + 0.5f * pw, y2 = cy + 0.5f * ph;
    float lx = fmaxf(x1, tx1), ly = fmaxf(y1, ty1);
    float rx = fminf(x2, tx2), ry = fminf(y2, ty2);
    float wx = fmaxf(rx - lx, 0.0f), wy = fmaxf(ry - ly, 0.0f);
    float inter = wx * wy;
    float a1 = (x2 - x1) * (y2 - y1);
    return inter / (a1 + tarea - inter);
}

__global__ void __launch_bounds__(TPB)
yolo_fused_kernel(const float* __restrict__ pred,
                  const float* __restrict__ tbox,
                  const float* __restrict__ tcls,
                  const void* __restrict__ objmap,
                  int n_cells, float n_batch, float* __restrict__ out)
{
    __shared__ float s_pred[2][TILE_FLOATS];      // 30 KB double buffer
    __shared__ float s_red[5 * (TPB / 32)];
    __shared__ double s_dred[TPB / 32];
    __shared__ double s_tot[5];
    __shared__ int s_last;

    const int tid  = threadIdx.x;
    const int lane = tid & 31;
    const int warp = tid >> 5;
    const int bid  = blockIdx.x;
    const int grid = gridDim.x;
    const int tiles = (n_cells + CPB - 1) / CPB;
    const int NT = (tiles - bid + grid - 1) / grid;   // tiles for this block (>=1)

    // ---- dtype detection: every block scans the SAME first 1KB (L2-broadcast) ----
    unsigned int wdet = ((const unsigned int*)objmap)[tid];
    int isf = __syncthreads_or(wdet == 0x3F800000u);
    int big = __syncthreads_or((wdet > 1u) && (wdet != 0x3F800000u));
    const int flag = isf ? 2 : (big ? 0 : 1);   // 2=float32, 0=bool bytes, 1=int32

    // ---- tile prefetch into smem buffer ----
    auto prefetch = [&](int tl, int buf) {
        int g  = bid + tl * grid;
        int cb = g * CPB;
        int cib = n_cells - cb; if (cib > CPB) cib = CPB;
        if (cib == CPB) {
            const float4* src = reinterpret_cast<const float4*>(pred + (size_t)cb * 30);
            unsigned int sbase = (unsigned int)__cvta_generic_to_shared(&s_pred[buf][0]);
            #pragma unroll
            for (int k = 0; k < 4; k++) {
                int i = tid + k * TPB;
                if (i < TILE_F4) cp_async16(sbase + i * 16, src + i);
            }
        } else {
            const float* srcb = pred + (size_t)cb * 30;
            for (int i = tid; i < cib * 30; i += TPB) s_pred[buf][i] = srcb[i];
        }
    };

    float accs[5] = {0.f, 0.f, 0.f, 0.f, 0.f};  // nobjcnt, reg, conf, noobj, cls

    prefetch(0, 0);
    cp_commit();
    if (NT > 1) prefetch(1, 1);
    cp_commit();

    for (int t = 0; t < NT; t++) {
        const int buf = t & 1;
        const int g  = bid + t * grid;
        const int cb = g * CPB;
        int cib = n_cells - cb; if (cib > CPB) cib = CPB;

        // ---- register prefetch for tile t (independent of smem) ----
        float2 tcv[5]; float obv[5]; int ccell[5], cr[5];
        float4 tb = make_float4(0.f, 0.f, 0.f, 0.f);
        float objB = 0.0f;
        const float2* tcls2 = reinterpret_cast<const float2*>(tcls + (size_t)cb * 20);

        if (cib == CPB) {
            int cc = tid / 10, rr = tid - (tid / 10) * 10;
            #pragma unroll
            for (int k = 0; k < 5; k++) {
                int i = tid + k * TPB;          // == cc*10 + rr
                tcv[k] = tcls2[i];
                ccell[k] = cc; cr[k] = rr;
                obv[k] = load_obj(objmap, cb + cc, flag);
                rr += 6; cc += 25;
                if (rr >= 10) { rr -= 10; ++cc; }   // 256 = 25*10 + 6
            }
            if (tid < CPB) {
                tb = reinterpret_cast<const float4*>(tbox)[cb + tid];
                objB = load_obj(objmap, cb + tid, flag);
            }
        } else {
            #pragma unroll
            for (int k = 0; k < 5; k++) {
                int i = tid + k * TPB;
                if (i < cib * 10) {
                    int cc = i / 10, rr = i - cc * 10;
                    tcv[k] = tcls2[i];
                    ccell[k] = cc; cr[k] = rr;
                    obv[k] = load_obj(objmap, cb + cc, flag);
                } else ccell[k] = -1;
            }
            if (tid < cib) {
                tb = reinterpret_cast<const float4*>(tbox)[cb + tid];
                objB = load_obj(objmap, cb + tid, flag);
            }
        }

        cp_wait1();
        __syncthreads();

        const float* sp = s_pred[buf];

        // ---- cls term ----
        if (cib == CPB) {
            #pragma unroll
            for (int k = 0; k < 5; k++) {
                float2 v = *reinterpret_cast<const float2*>(&sp[ccell[k] * 30 + 10 + 2 * cr[k]]);
                float dx = v.x - tcv[k].x, dy = v.y - tcv[k].y;
                accs[4] += obv[k] * (dx * dx + dy * dy);
            }
        } else {
            #pragma unroll
            for (int k = 0; k < 5; k++) {
                if (ccell[k] >= 0) {
                    float2 v = *reinterpret_cast<const float2*>(&sp[ccell[k] * 30 + 10 + 2 * cr[k]]);
                    float dx = v.x - tcv[k].x, dy = v.y - tcv[k].y;
                    accs[4] += obv[k] * (dx * dx + dy * dy);
                }
            }
        }

        // ---- per-cell noobj + IoU/reg/conf ----
        if (tid < cib) {
            const float* bb = &sp[tid * 30];
            float2 p01 = *reinterpret_cast<const float2*>(bb + 0);
            float2 p23 = *reinterpret_cast<const float2*>(bb + 2);
            float2 p45 = *reinterpret_cast<const float2*>(bb + 4);
            float2 p67 = *reinterpret_cast<const float2*>(bb + 6);
            float2 p89 = *reinterpret_cast<const float2*>(bb + 8);
            float b1x = p01.x, b1y = p01.y, b1w = p23.x, b1h = p23.y, b1c = p45.x;
            float b2x = p45.y, b2y = p67.x, b2w = p67.y, b2h = p89.x, b2c = p89.y;

            accs[0] += objB;
            float sq = b1x*b1x + b1y*b1y + b1w*b1w + b1h*b1h + b1c*b1c
                     + b2x*b2x + b2y*b2y + b2w*b2w + b2h*b2h + b2c*b2c;
            accs[3] += (1.0f - objB) * sq;

            if (objB > 0.0f) {
                const float invS = 1.0f / 14.0f;
                float tcx = tb.x * invS, tcy = tb.y * invS;
                float tx1 = tcx - 0.5f * tb.z, ty1 = tcy - 0.5f * tb.w;
                float tx2 = tcx + 0.5f * tb.z, ty2 = tcy + 0.5f * tb.w;
                float tarea = (tx2 - tx1) * (ty2 - ty1);

                float iou1 = iou_pred_vs_tgt(b1x, b1y, b1w, b1h, tx1, ty1, tx2, ty2, tarea);
                float iou2 = iou_pred_vs_tgt(b2x, b2y, b2w, b2h, tx1, ty1, tx2, ty2, tarea);

                bool take1 = (iou1 >= iou2);
                float bx = take1 ? b1x : b2x;
                float by = take1 ? b1y : b2y;
                float bw = take1 ? b1w : b2w;
                float bh = take1 ? b1h : b2h;
                float bc = take1 ? b1c : b2c;
                float biou = take1 ? iou1 : iou2;

                float dx = bx - tb.x;
                float dy = by - tb.y;
                float dw = sqrtf(bw) - sqrtf(tb.z);
                float dh = sqrtf(bh) - sqrtf(tb.w);
                accs[1] += dx * dx + dy * dy + dw * dw + dh * dh;

                float dc = bc - biou;
                accs[2] += dc * dc;
            }
        }

        __syncthreads();
        if (t + 2 < NT) prefetch(t + 2, buf);
        cp_commit();
    }

    // ---- Block reduction of 5 accumulators -> SoA partials ----
    #pragma unroll
    for (int k = 0; k < 5; k++) {
        float v = accs[k];
        #pragma unroll
        for (int off = 16; off > 0; off >>= 1)
            v += __shfl_down_sync(0xffffffffu, v, off);
        if (lane == 0) s_red[k * (TPB / 32) + warp] = v;
    }
    __syncthreads();
    if (tid < 5) {
        float v = 0.0f;
        #pragma unroll
        for (int w2 = 0; w2 < TPB / 32; w2++)
            v += s_red[tid * (TPB / 32) + w2];
        g_partials[tid * grid + bid] = v;
    }

    // ---- Last-block finalize ----
    if (tid == 0) {
        __threadfence();
        unsigned int old = atomicInc(&g_counter, (unsigned int)(grid - 1));
        s_last = (old == (unsigned int)(grid - 1)) ? 1 : 0;
    }
    __syncthreads();
    if (!s_last) return;

    volatile float* gp = g_partials;
    double acc[5] = {0.0, 0.0, 0.0, 0.0, 0.0};
    for (int i = tid; i < grid; i += TPB) {
        #pragma unroll
        for (int k = 0; k < 5; k++)
            acc[k] += (double)gp[k * grid + i];
    }
    #pragma unroll
    for (int k = 0; k < 5; k++) {
        double v = acc[k];
        #pragma unroll
        for (int off = 16; off > 0; off >>= 1)
            v += __shfl_down_sync(0xffffffffu, v, off);
        if (lane == 0) s_dred[warp] = v;
        __syncthreads();
        if (tid == 0) {
            double tsum = 0.0;
            #pragma unroll
            for (int w2 = 0; w2 < TPB / 32; w2++) tsum += s_dred[w2];
            s_tot[k] = tsum;
        }
        __syncthreads();
    }

    if (tid == 0) {
        double n_obj   = s_tot[0];
        double n_noobj = (double)n_cells - n_obj;
        double reg_loss   = 5.0 * s_tot[1] / n_obj;
        double conf_loss  = s_tot[2] / n_obj;
        double noobj_loss = 0.5 * s_tot[3] / n_noobj;
        double cls_loss   = s_tot[4] / (double)n_batch;
        double total = reg_loss + conf_loss + noobj_loss + cls_loss;
        out[0] = (float)total;
        out[1] = (float)reg_loss;
        out[2] = (float)conf_loss;
        out[3] = (float)noobj_loss;
        out[4] = (float)cls_loss;
    }
}

extern "C" void kernel_launch(void* const* d_in, const int* in_sizes, int n_in,
                              void* d_out, int out_size)
{
    const float* pred = (const float*)d_in[0];
    const float* tbox = (const float*)d_in[1];
    const float* tcls = (const float*)d_in[2];
    const void*  objmap = d_in[3];
    float* out = (float*)d_out;

    const int n_cells = in_sizes[3];                  // N * S * S
    const int n_batch = in_sizes[0] / (14 * 14 * 30);
    const int tiles = (n_cells + CPB - 1) / CPB;

    int grid = 148 * 6;                               // ~6 CTAs/SM, single wave
    if (grid > tiles) grid = tiles;
    if (grid > MAX_GRID) grid = MAX_GRID;

    yolo_fused_kernel<<<grid, TPB>>>(pred, tbox, tcls, objmap,
                                     n_cells, (float)n_batch, out);
}

// round 8
// speedup vs baseline: 1.3240x; 1.3240x over previous
#include <cuda_runtime.h>

#define TPB 256
#define CPB 256            // cells per block (8 warps x 32 cells)
#define MAX_GRID 16384

// SoA per-block partials: [k * grid + bid]
__device__ float g_partials[5 * MAX_GRID];
__device__ unsigned int g_counter = 0;   // atomicInc wraps -> replay-safe

__device__ __forceinline__ void cp_async16(unsigned int saddr, const void* gptr) {
    asm volatile("cp.async.cg.shared.global [%0], [%1], 16;" :: "r"(saddr), "l"(gptr));
}
__device__ __forceinline__ void cp_commit() {
    asm volatile("cp.async.commit_group;" ::: "memory");
}
__device__ __forceinline__ void cp_wait_1() {
    asm volatile("cp.async.wait_group 1;" ::: "memory");
}
__device__ __forceinline__ void cp_wait_0() {
    asm volatile("cp.async.wait_group 0;" ::: "memory");
}

__device__ __forceinline__ float load_obj(const void* objmap, int idx, int flag) {
    if (flag == 2) return ((const float*)objmap)[idx];
    if (flag == 1) return (((const int*)objmap)[idx] != 0) ? 1.0f : 0.0f;
    return ((const unsigned char*)objmap)[idx] ? 1.0f : 0.0f;
}

__device__ __forceinline__ float iou_pred_vs_tgt(
    float px, float py, float pw, float ph,
    float tx1, float ty1, float tx2, float ty2, float tarea)
{
    const float invS = 1.0f / 14.0f;
    float cx = px * invS, cy = py * invS;
    float x1 = cx - 0.5f * pw, y1 = cy - 0.5f * ph;
    float x2 = cx + 0.5f * pw, y2 = cy + 0.5f * ph;
    float lx = fmaxf(x1, tx1), ly = fmaxf(y1, ty1);
    float rx = fminf(x2, tx2), ry = fminf(y2, ty2);
    float wx = fmaxf(rx - lx, 0.0f), wy = fmaxf(ry - ly, 0.0f);
    float inter = wx * wy;
    float a1 = (x2 - x1) * (y2 - y1);
    return inter / (a1 + tarea - inter);
}

__global__ void __launch_bounds__(TPB, 6)
yolo_fused_kernel(const float* __restrict__ pred,
                  const float* __restrict__ tbox,
                  const float* __restrict__ tcls,
                  const void* __restrict__ objmap,
                  int n_cells, float n_batch, float* __restrict__ out)
{
    __shared__ float s_pred[CPB * 30];        // 30 KB
    __shared__ float s_red[5 * (TPB / 32)];
    __shared__ double s_dred[TPB / 32];
    __shared__ double s_tot[5];
    __shared__ int s_last;

    const int tid  = threadIdx.x;
    const int lane = tid & 31;
    const int warp = tid >> 5;
    const int bid  = blockIdx.x;
    const int grid = gridDim.x;
    const int cellbase = bid * CPB;
    int cib = n_cells - cellbase;
    if (cib > CPB) cib = CPB;

    // ---- dtype detection (same 1KB scan by every block; L2-broadcast) ----
    unsigned int wdet = ((const unsigned int*)objmap)[tid];
    int isf = __syncthreads_or(wdet == 0x3F800000u);
    int big = __syncthreads_or((wdet > 1u) && (wdet != 0x3F800000u));
    const int flag = isf ? 2 : (big ? 0 : 1);   // 2=float32, 0=bool bytes, 1=int32

    float acc_cls = 0.f, acc_reg = 0.f, acc_conf = 0.f, acc_nobjcnt = 0.f, acc_noobj = 0.f;

    if (cib == CPB) {
        // ================= FAST PATH: warp-autonomous, 2-stage cp.async =================
        const int wbase = warp * 32;                         // warp's first cell in tile
        const float* predg = pred + (size_t)(cellbase + wbase) * 30;
        unsigned int sbase = (unsigned int)__cvta_generic_to_shared(&s_pred[wbase * 30]);

        // stage pred halves via cp.async (reg-free): half = 16 cells = 480 floats = 120 f4
        #pragma unroll
        for (int h = 0; h < 2; h++) {
            const float4* src = reinterpret_cast<const float4*>(predg + h * 480);
            #pragma unroll
            for (int k = 0; k < 4; k++) {
                int j = lane + k * 32;
                if (j < 120) cp_async16(sbase + (unsigned)(h * 480 + j * 4) * 4u, src + j);
            }
            cp_commit();
        }

        // tcls per half -> registers (3 f4 per lane per half, transient)
        const float4* tclsg4 = reinterpret_cast<const float4*>(tcls + (size_t)(cellbase + wbase) * 20);
        float4 t0[3], t1[3];
        #pragma unroll
        for (int k = 0; k < 3; k++) {
            int j = lane + k * 32;
            t0[k] = (j < 80) ? tclsg4[j]      : make_float4(0.f, 0.f, 0.f, 0.f);
            t1[k] = (j < 80) ? tclsg4[80 + j] : make_float4(0.f, 0.f, 0.f, 0.f);
        }

        // per-lane cell data (lane <-> cell wbase+lane)
        float4 tb = reinterpret_cast<const float4*>(tbox)[cellbase + wbase + lane];
        float objv = load_obj(objmap, cellbase + wbase + lane, flag);

        // cls for one half: strip of 80 f4 (16 cells x 5 f4); j = lane + 32k
        auto cls_half = [&](int h, const float4* tt) {
            int j = lane;
            int c = lane / 5;           // cell within half (0..15)
            int r = lane - c * 5;       // f4 index within cell (0..4)
            #pragma unroll
            for (int k = 0; k < 3; k++) {
                int cc = (c < 15) ? c : 15;
                float obj = __shfl_sync(0xffffffffu, objv, h * 16 + cc);
                if (j < 80) {
                    const float* pp = &s_pred[(wbase + h * 16 + c) * 30 + 10 + 4 * r];
                    float2 a = *reinterpret_cast<const float2*>(pp);
                    float2 b = *reinterpret_cast<const float2*>(pp + 2);
                    float d0 = a.x - tt[k].x, d1 = a.y - tt[k].y;
                    float d2 = b.x - tt[k].z, d3 = b.y - tt[k].w;
                    acc_cls += obj * (d0 * d0 + d1 * d1 + d2 * d2 + d3 * d3);
                }
                j += 32; c += 6; r += 2;            // 32 = 6*5 + 2
                if (r >= 5) { r -= 5; ++c; }
            }
        };

        cp_wait_1(); __syncwarp();
        cls_half(0, t0);
        cp_wait_0(); __syncwarp();
        cls_half(1, t1);

        // phase B: lane <-> cell, everything from warp's smem region + regs
        {
            const float* bb = &s_pred[(wbase + lane) * 30];
            float2 p01 = *reinterpret_cast<const float2*>(bb + 0);
            float2 p23 = *reinterpret_cast<const float2*>(bb + 2);
            float2 p45 = *reinterpret_cast<const float2*>(bb + 4);
            float2 p67 = *reinterpret_cast<const float2*>(bb + 6);
            float2 p89 = *reinterpret_cast<const float2*>(bb + 8);
            float b1x = p01.x, b1y = p01.y, b1w = p23.x, b1h = p23.y, b1c = p45.x;
            float b2x = p45.y, b2y = p67.x, b2w = p67.y, b2h = p89.x, b2c = p89.y;

            acc_nobjcnt = objv;
            float sq = b1x*b1x + b1y*b1y + b1w*b1w + b1h*b1h + b1c*b1c
                     + b2x*b2x + b2y*b2y + b2w*b2w + b2h*b2h + b2c*b2c;
            acc_noobj = (1.0f - objv) * sq;

            if (objv > 0.0f) {
                const float invS = 1.0f / 14.0f;
                float tcx = tb.x * invS, tcy = tb.y * invS;
                float tx1 = tcx - 0.5f * tb.z, ty1 = tcy - 0.5f * tb.w;
                float tx2 = tcx + 0.5f * tb.z, ty2 = tcy + 0.5f * tb.w;
                float tarea = (tx2 - tx1) * (ty2 - ty1);

                float iou1 = iou_pred_vs_tgt(b1x, b1y, b1w, b1h, tx1, ty1, tx2, ty2, tarea);
                float iou2 = iou_pred_vs_tgt(b2x, b2y, b2w, b2h, tx1, ty1, tx2, ty2, tarea);

                bool take1 = (iou1 >= iou2);
                float bx = take1 ? b1x : b2x;
                float by = take1 ? b1y : b2y;
                float bw = take1 ? b1w : b2w;
                float bh = take1 ? b1h : b2h;
                float bc = take1 ? b1c : b2c;
                float biou = take1 ? iou1 : iou2;

                float dx = bx - tb.x;
                float dy = by - tb.y;
                float dw = sqrtf(bw) - sqrtf(tb.z);
                float dh = sqrtf(bh) - sqrtf(tb.w);
                acc_reg = dx * dx + dy * dy + dw * dw + dh * dh;

                float dc = bc - biou;
                acc_conf = dc * dc;
            }
        }
    } else {
        // ================= SLOW PATH: partial tile (not hit at this shape) =================
        const float* predb = pred + (size_t)cellbase * 30;
        for (int i = tid; i < cib * 30; i += TPB) s_pred[i] = predb[i];
        __syncthreads();

        const float2* tcls2 = reinterpret_cast<const float2*>(tcls + (size_t)cellbase * 20);
        for (int i = tid; i < cib * 10; i += TPB) {
            int cell = i / 10, r = i - cell * 10;
            float2 t = tcls2[i];
            float2 v = *reinterpret_cast<const float2*>(&s_pred[cell * 30 + 10 + 2 * r]);
            float obj = load_obj(objmap, cellbase + cell, flag);
            float dx = v.x - t.x, dy = v.y - t.y;
            acc_cls += obj * (dx * dx + dy * dy);
        }
        if (tid < cib) {
            float objv = load_obj(objmap, cellbase + tid, flag);
            float4 tb = reinterpret_cast<const float4*>(tbox)[cellbase + tid];
            const float* bb = &s_pred[tid * 30];
            float b1x = bb[0], b1y = bb[1], b1w = bb[2], b1h = bb[3], b1c = bb[4];
            float b2x = bb[5], b2y = bb[6], b2w = bb[7], b2h = bb[8], b2c = bb[9];

            acc_nobjcnt = objv;
            float sq = b1x*b1x + b1y*b1y + b1w*b1w + b1h*b1h + b1c*b1c
                     + b2x*b2x + b2y*b2y + b2w*b2w + b2h*b2h + b2c*b2c;
            acc_noobj = (1.0f - objv) * sq;

            if (objv > 0.0f) {
                const float invS = 1.0f / 14.0f;
                float tcx = tb.x * invS, tcy = tb.y * invS;
                float tx1 = tcx - 0.5f * tb.z, ty1 = tcy - 0.5f * tb.w;
                float tx2 = tcx + 0.5f * tb.z, ty2 = tcy + 0.5f * tb.w;
                float tarea = (tx2 - tx1) * (ty2 - ty1);
                float iou1 = iou_pred_vs_tgt(b1x, b1y, b1w, b1h, tx1, ty1, tx2, ty2, tarea);
                float iou2 = iou_pred_vs_tgt(b2x, b2y, b2w, b2h, tx1, ty1, tx2, ty2, tarea);
                bool take1 = (iou1 >= iou2);
                float bx = take1 ? b1x : b2x;
                float by = take1 ? b1y : b2y;
                float bw = take1 ? b1w : b2w;
                float bh = take1 ? b1h : b2h;
                float bc = take1 ? b1c : b2c;
                float biou = take1 ? iou1 : iou2;
                float dx = bx - tb.x, dy = by - tb.y;
                float dw = sqrtf(bw) - sqrtf(tb.z);
                float dh = sqrtf(bh) - sqrtf(tb.w);
                acc_reg = dx * dx + dy * dy + dw * dw + dh * dh;
                float dc = bc - biou;
                acc_conf = dc * dc;
            }
        }
    }

    // ---- Block reduction of 5 accumulators -> SoA partials ----
    float vals[5] = {acc_nobjcnt, acc_reg, acc_conf, acc_noobj, acc_cls};
    #pragma unroll
    for (int k = 0; k < 5; k++) {
        float v = vals[k];
        #pragma unroll
        for (int off = 16; off > 0; off >>= 1)
            v += __shfl_down_sync(0xffffffffu, v, off);
        if (lane == 0) s_red[k * (TPB / 32) + warp] = v;
    }
    __syncthreads();
    if (tid < 5) {
        float v = 0.0f;
        #pragma unroll
        for (int w2 = 0; w2 < TPB / 32; w2++)
            v += s_red[tid * (TPB / 32) + w2];
        g_partials[tid * grid + bid] = v;
    }

    // ---- Last-block finalize ----
    if (tid == 0) {
        __threadfence();
        unsigned int old = atomicInc(&g_counter, (unsigned int)(grid - 1));
        s_last = (old == (unsigned int)(grid - 1)) ? 1 : 0;
    }
    __syncthreads();
    if (!s_last) return;

    volatile float* gp = g_partials;
    double acc[5] = {0.0, 0.0, 0.0, 0.0, 0.0};
    for (int i = tid; i < grid; i += TPB) {
        #pragma unroll
        for (int k = 0; k < 5; k++)
            acc[k] += (double)gp[k * grid + i];
    }
    #pragma unroll
    for (int k = 0; k < 5; k++) {
        double v = acc[k];
        #pragma unroll
        for (int off = 16; off > 0; off >>= 1)
            v += __shfl_down_sync(0xffffffffu, v, off);
        if (lane == 0) s_dred[warp] = v;
        __syncthreads();
        if (tid == 0) {
            double tsum = 0.0;
            #pragma unroll
            for (int w2 = 0; w2 < TPB / 32; w2++) tsum += s_dred[w2];
            s_tot[k] = tsum;
        }
        __syncthreads();
    }

    if (tid == 0) {
        double n_obj   = s_tot[0];
        double n_noobj = (double)n_cells - n_obj;
        double reg_loss   = 5.0 * s_tot[1] / n_obj;
        double conf_loss  = s_tot[2] / n_obj;
        double noobj_loss = 0.5 * s_tot[3] / n_noobj;
        double cls_loss   = s_tot[4] / (double)n_batch;
        double total = reg_loss + conf_loss + noobj_loss + cls_loss;
        out[0] = (float)total;
        out[1] = (float)reg_loss;
        out[2] = (float)conf_loss;
        out[3] = (float)noobj_loss;
        out[4] = (float)cls_loss;
    }
}

extern "C" void kernel_launch(void* const* d_in, const int* in_sizes, int n_in,
                              void* d_out, int out_size)
{
    const float* pred = (const float*)d_in[0];
    const float* tbox = (const float*)d_in[1];
    const float* tcls = (const float*)d_in[2];
    const void*  objmap = d_in[3];
    float* out = (float*)d_out;

    const int n_cells = in_sizes[3];                  // N * S * S
    const int n_batch = in_sizes[0] / (14 * 14 * 30);
    int grid = (n_cells + CPB - 1) / CPB;
    if (grid > MAX_GRID) grid = MAX_GRID;             // not reachable at this shape

    yolo_fused_kernel<<<grid, TPB>>>(pred, tbox, tcls, objmap,
                                     n_cells, (float)n_batch, out);
}

// round 9
// speedup vs baseline: 1.3708x; 1.0353x over previous
#include <cuda_runtime.h>

#define TPB 256
#define CPB 256          // cells per block
#define MAX_GRID 16384

// SoA per-block partials: [k * grid + bid], k in {nobj_count, reg, conf, noobj, cls}
__device__ float g_partials[5 * MAX_GRID];
__device__ unsigned int g_counter = 0;   // atomicInc wraps back to 0 -> replay-safe

__device__ __forceinline__ float iou_pred_vs_tgt(
    float px, float py, float pw, float ph,
    float tx1, float ty1, float tx2, float ty2, float tarea)
{
    const float invS = 1.0f / 14.0f;
    float cx = px * invS, cy = py * invS;
    float x1 = cx - 0.5f * pw, y1 = cy - 0.5f * ph;
    float x2 = cx + 0.5f * pw, y2 = cy + 0.5f * ph;
    float lx = fmaxf(x1, tx1), ly = fmaxf(y1, ty1);
    float rx = fminf(x2, tx2), ry = fminf(y2, ty2);
    float wx = fmaxf(rx - lx, 0.0f), wy = fmaxf(ry - ly, 0.0f);
    float inter = wx * wy;
    float a1 = (x2 - x1) * (y2 - y1);
    return inter / (a1 + tarea - inter);
}

__global__ void __launch_bounds__(TPB, 6)
yolo_fused_kernel(const float* __restrict__ pred,
                  const float* __restrict__ tbox,
                  const float* __restrict__ tcls,
                  const void* __restrict__ objmap,
                  int n_cells, float n_batch, float* __restrict__ out)
{
    __shared__ float s_pred[CPB * 30];        // 30 KB, mirrors gmem layout
    __shared__ float s_obj[CPB];
    __shared__ float s_red[5 * (TPB / 32)];
    __shared__ double s_dred[TPB / 32];
    __shared__ double s_tot[5];
    __shared__ int s_last;

    const int tid  = threadIdx.x;
    const int lane = tid & 31;
    const int warp = tid >> 5;
    const int bid  = blockIdx.x;
    const int grid = gridDim.x;
    const int cellbase = bid * CPB;
    int cib = n_cells - cellbase;
    if (cib > CPB) cib = CPB;

    // ---- dtype detection: every block scans the SAME first 1KB (L2-broadcast) ----
    unsigned int wdet = ((const unsigned int*)objmap)[tid];
    int isf = __syncthreads_or(wdet == 0x3F800000u);
    int big = __syncthreads_or((wdet > 1u) && (wdet != 0x3F800000u));
    const int flag = isf ? 2 : (big ? 0 : 1);   // 2=float32, 0=bool bytes, 1=int32

    // ---- load object map for this block's cells ----
    float o_mine = 0.0f;
    if (tid < cib) {
        int idx = cellbase + tid;
        if (flag == 2)      o_mine = ((const float*)objmap)[idx];
        else if (flag == 1) o_mine = (((const int*)objmap)[idx] != 0) ? 1.0f : 0.0f;
        else                o_mine = ((const unsigned char*)objmap)[idx] ? 1.0f : 0.0f;
        s_obj[tid] = o_mine;
    }

    // ---- Phase A1: stage pred tile to SMEM (pure float4 copy, MLP=8) ----
    if (cib == CPB) {
        const float4* pred4 = reinterpret_cast<const float4*>(pred + (size_t)cellbase * 30);
        float4* s_pred4 = reinterpret_cast<float4*>(s_pred);
        #pragma unroll
        for (int k = 0; k < 8; k++) {
            int i = tid + k * TPB;
            if (i < (CPB * 30) / 4) s_pred4[i] = pred4[i];
        }
    } else {
        const float* predb = pred + (size_t)cellbase * 30;
        for (int i = tid; i < cib * 30; i += TPB) s_pred[i] = predb[i];
    }

    // ---- tbox prefetch: ONLY for obj cells (predicated LDG; saves ~70% of tbox traffic) ----
    float4 tb = make_float4(0.f, 0.f, 0.f, 0.f);
    if (tid < cib && o_mine > 0.0f)
        tb = reinterpret_cast<const float4*>(tbox)[cellbase + tid];

    __syncthreads();

    // ---- Phase A2: cls loop; tcls load predicated on obj (saves ~60% of tcls traffic) ----
    float acc_cls = 0.0f;
    const float2* tcls2 = reinterpret_cast<const float2*>(tcls + (size_t)cellbase * 20);
    if (cib == CPB) {
        int cell = tid / 10;
        int r = tid - cell * 10;          // cls f2 index within cell (0..9)
        #pragma unroll
        for (int k = 0; k < 10; k++) {
            int i = tid + k * TPB;        // == cell*10 + r
            float obj = s_obj[cell];
            float2 t = make_float2(0.f, 0.f);
            if (obj > 0.0f) t = tcls2[i];             // @P LDG.64, no branch arms
            float2 v = *reinterpret_cast<const float2*>(&s_pred[cell * 30 + 10 + 2 * r]);
            float dx = v.x - t.x, dy = v.y - t.y;
            acc_cls += obj * (dx * dx + dy * dy);     // obj=0 -> contributes 0 (t=0 keeps it finite)
            r += 6; cell += 25;
            if (r >= 10) { r -= 10; ++cell; }         // 256 = 25*10 + 6
        }
    } else {
        for (int i = tid; i < cib * 10; i += TPB) {
            int cell = i / 10;
            int r = i - cell * 10;
            float obj = s_obj[cell];
            float2 t = make_float2(0.f, 0.f);
            if (obj > 0.0f) t = tcls2[i];
            float2 v = *reinterpret_cast<const float2*>(&s_pred[cell * 30 + 10 + 2 * r]);
            float dx = v.x - t.x, dy = v.y - t.y;
            acc_cls += obj * (dx * dx + dy * dy);
        }
    }

    // ---- Phase B: per-cell noobj squares + IoU/reg/conf from SMEM ----
    float acc_reg = 0.0f, acc_conf = 0.0f, acc_nobjcnt = 0.0f, acc_noobj = 0.0f;
    if (tid < cib) {
        float obj = o_mine;
        acc_nobjcnt = obj;

        const float* bb = &s_pred[tid * 30];
        float b1x = bb[0], b1y = bb[1], b1w = bb[2], b1h = bb[3], b1c = bb[4];
        float b2x = bb[5], b2y = bb[6], b2w = bb[7], b2h = bb[8], b2c = bb[9];

        float sq = b1x * b1x + b1y * b1y + b1w * b1w + b1h * b1h + b1c * b1c
                 + b2x * b2x + b2y * b2y + b2w * b2w + b2h * b2h + b2c * b2c;
        acc_noobj = (1.0f - obj) * sq;

        if (obj > 0.0f) {
            const float invS = 1.0f / 14.0f;
            float tcx = tb.x * invS, tcy = tb.y * invS;
            float tx1 = tcx - 0.5f * tb.z, ty1 = tcy - 0.5f * tb.w;
            float tx2 = tcx + 0.5f * tb.z, ty2 = tcy + 0.5f * tb.w;
            float tarea = (tx2 - tx1) * (ty2 - ty1);

            float iou1 = iou_pred_vs_tgt(b1x, b1y, b1w, b1h, tx1, ty1, tx2, ty2, tarea);
            float iou2 = iou_pred_vs_tgt(b2x, b2y, b2w, b2h, tx1, ty1, tx2, ty2, tarea);

            bool take1 = (iou1 >= iou2);
            float bx = take1 ? b1x : b2x;
            float by = take1 ? b1y : b2y;
            float bw = take1 ? b1w : b2w;
            float bh = take1 ? b1h : b2h;
            float bc = take1 ? b1c : b2c;
            float biou = take1 ? iou1 : iou2;

            float dx = bx - tb.x;
            float dy = by - tb.y;
            float dw = sqrtf(bw) - sqrtf(tb.z);
            float dh = sqrtf(bh) - sqrtf(tb.w);
            acc_reg = dx * dx + dy * dy + dw * dw + dh * dh;

            float dc = bc - biou;
            acc_conf = dc * dc;
        }
    }

    // ---- Block reduction of 5 accumulators -> SoA partials ----
    float vals[5] = {acc_nobjcnt, acc_reg, acc_conf, acc_noobj, acc_cls};
    #pragma unroll
    for (int k = 0; k < 5; k++) {
        float v = vals[k];
        #pragma unroll
        for (int off = 16; off > 0; off >>= 1)
            v += __shfl_down_sync(0xffffffffu, v, off);
        if (lane == 0) s_red[k * (TPB / 32) + warp] = v;
    }
    __syncthreads();
    if (tid < 5) {
        float v = 0.0f;
        #pragma unroll
        for (int w2 = 0; w2 < TPB / 32; w2++)
            v += s_red[tid * (TPB / 32) + w2];
        g_partials[tid * grid + bid] = v;
    }

    // ---- Last-block finalize ----
    if (tid == 0) {
        __threadfence();
        unsigned int old = atomicInc(&g_counter, (unsigned int)(grid - 1));
        s_last = (old == (unsigned int)(grid - 1)) ? 1 : 0;
    }
    __syncthreads();
    if (!s_last) return;

    volatile float* gp = g_partials;
    double acc[5] = {0.0, 0.0, 0.0, 0.0, 0.0};
    for (int i = tid; i < grid; i += TPB) {
        #pragma unroll
        for (int k = 0; k < 5; k++)
            acc[k] += (double)gp[k * grid + i];
    }
    #pragma unroll
    for (int k = 0; k < 5; k++) {
        double v = acc[k];
        #pragma unroll
        for (int off = 16; off > 0; off >>= 1)
            v += __shfl_down_sync(0xffffffffu, v, off);
        if (lane == 0) s_dred[warp] = v;
        __syncthreads();
        if (tid == 0) {
            double tsum = 0.0;
            #pragma unroll
            for (int w2 = 0; w2 < TPB / 32; w2++) tsum += s_dred[w2];
            s_tot[k] = tsum;
        }
        __syncthreads();
    }

    if (tid == 0) {
        double n_obj   = s_tot[0];
        double n_noobj = (double)n_cells - n_obj;
        double reg_loss   = 5.0 * s_tot[1] / n_obj;
        double conf_loss  = s_tot[2] / n_obj;
        double noobj_loss = 0.5 * s_tot[3] / n_noobj;
        double cls_loss   = s_tot[4] / (double)n_batch;
        double total = reg_loss + conf_loss + noobj_loss + cls_loss;
        out[0] = (float)total;
        out[1] = (float)reg_loss;
        out[2] = (float)conf_loss;
        out[3] = (float)noobj_loss;
        out[4] = (float)cls_loss;
    }
}

extern "C" void kernel_launch(void* const* d_in, const int* in_sizes, int n_in,
                              void* d_out, int out_size)
{
    const float* pred = (const float*)d_in[0];
    const float* tbox = (const float*)d_in[1];
    const float* tcls = (const float*)d_in[2];
    const void*  objmap = d_in[3];
    float* out = (float*)d_out;

    const int n_cells = in_sizes[3];                  // N * S * S
    const int n_batch = in_sizes[0] / (14 * 14 * 30);
    int grid = (n_cells + CPB - 1) / CPB;
    if (grid > MAX_GRID) grid = MAX_GRID;             // not reachable at this shape

    yolo_fused_kernel<<<grid, TPB>>>(pred, tbox, tcls, objmap,
                                     n_cells, (float)n_batch, out);
}

// round 10
// speedup vs baseline: 1.3778x; 1.0052x over previous
#include <cuda_runtime.h>

#define TPB 512
#define CPB 512          // cells per block
#define MAX_GRID 16384

// SoA per-block partials: [k * grid + bid], k in {nobj_count, reg, conf, noobj, cls}
__device__ float g_partials[5 * MAX_GRID];
__device__ unsigned int g_counter = 0;   // atomicInc wraps back to 0 -> replay-safe

__device__ __forceinline__ void cp_async16(unsigned int saddr, const void* gptr) {
    asm volatile("cp.async.cg.shared.global [%0], [%1], 16;" :: "r"(saddr), "l"(gptr));
}
__device__ __forceinline__ void cp_commit() {
    asm volatile("cp.async.commit_group;" ::: "memory");
}
__device__ __forceinline__ void cp_wait_all() {
    asm volatile("cp.async.wait_group 0;" ::: "memory");
}

__device__ __forceinline__ float iou_pred_vs_tgt(
    float px, float py, float pw, float ph,
    float tx1, float ty1, float tx2, float ty2, float tarea)
{
    const float invS = 1.0f / 14.0f;
    float cx = px * invS, cy = py * invS;
    float x1 = cx - 0.5f * pw, y1 = cy - 0.5f * ph;
    float x2 = cx + 0.5f * pw, y2 = cy + 0.5f * ph;
    float lx = fmaxf(x1, tx1), ly = fmaxf(y1, ty1);
    float rx = fminf(x2, tx2), ry = fminf(y2, ty2);
    float wx = fmaxf(rx - lx, 0.0f), wy = fmaxf(ry - ly, 0.0f);
    float inter = wx * wy;
    float a1 = (x2 - x1) * (y2 - y1);
    return inter / (a1 + tarea - inter);
}

__global__ void __launch_bounds__(TPB, 3)
yolo_fused_kernel(const float* __restrict__ pred,
                  const float* __restrict__ tbox,
                  const float* __restrict__ tcls,
                  const void* __restrict__ objmap,
                  int n_cells, float n_batch, float* __restrict__ out)
{
    __shared__ float s_pred[CPB * 30];        // 60 KB, mirrors gmem layout
    __shared__ float s_obj[CPB];
    __shared__ float s_red[5 * (TPB / 32)];
    __shared__ double s_dred[TPB / 32];
    __shared__ double s_tot[5];
    __shared__ int s_last;

    const int tid  = threadIdx.x;
    const int lane = tid & 31;
    const int warp = tid >> 5;
    const int bid  = blockIdx.x;
    const int grid = gridDim.x;
    const int cellbase = bid * CPB;
    int cib = n_cells - cellbase;
    if (cib > CPB) cib = CPB;

    // ---- dtype detection: every block scans the SAME first 2KB (L2-broadcast) ----
    unsigned int wdet = ((const unsigned int*)objmap)[tid];
    int isf = __syncthreads_or(wdet == 0x3F800000u);
    int big = __syncthreads_or((wdet > 1u) && (wdet != 0x3F800000u));
    const int flag = isf ? 2 : (big ? 0 : 1);   // 2=float32, 0=bool bytes, 1=int32

    // ---- Phase A1: stage pred tile to SMEM via cp.async (reg-free, L1-bypass) ----
    if (cib == CPB) {
        const float4* pred4 = reinterpret_cast<const float4*>(pred + (size_t)cellbase * 30);
        unsigned int sbase = (unsigned int)__cvta_generic_to_shared(&s_pred[0]);
        #pragma unroll
        for (int k = 0; k < 8; k++) {
            int i = tid + k * TPB;
            if (i < (CPB * 30) / 4) cp_async16(sbase + (unsigned)i * 16u, pred4 + i);
        }
    } else {
        const float* predb = pred + (size_t)cellbase * 30;
        for (int i = tid; i < cib * 30; i += TPB) s_pred[i] = predb[i];
    }
    cp_commit();

    // ---- obj map + predicated tbox prefetch (independent of cp.async) ----
    float o_mine = 0.0f;
    if (tid < cib) {
        int idx = cellbase + tid;
        if (flag == 2)      o_mine = ((const float*)objmap)[idx];
        else if (flag == 1) o_mine = (((const int*)objmap)[idx] != 0) ? 1.0f : 0.0f;
        else                o_mine = ((const unsigned char*)objmap)[idx] ? 1.0f : 0.0f;
        s_obj[tid] = o_mine;
    }
    float4 tb = make_float4(0.f, 0.f, 0.f, 0.f);
    if (tid < cib && o_mine > 0.0f)
        tb = reinterpret_cast<const float4*>(tbox)[cellbase + tid];

    cp_wait_all();
    __syncthreads();

    // ---- Phase A2: cls loop; tcls load predicated on obj ----
    float acc_cls = 0.0f;
    const float2* tcls2 = reinterpret_cast<const float2*>(tcls + (size_t)cellbase * 20);
    if (cib == CPB) {
        int cell = tid / 10;
        int r = tid - cell * 10;          // cls f2 index within cell (0..9)
        #pragma unroll
        for (int k = 0; k < 10; k++) {
            int i = tid + k * TPB;        // == cell*10 + r
            float obj = s_obj[cell];
            float2 t = make_float2(0.f, 0.f);
            if (obj > 0.0f) t = tcls2[i];             // @P LDG.64
            float2 v = *reinterpret_cast<const float2*>(&s_pred[cell * 30 + 10 + 2 * r]);
            float dx = v.x - t.x, dy = v.y - t.y;
            acc_cls += obj * (dx * dx + dy * dy);
            cell += 51; r += 2;
            if (r >= 10) { r -= 10; ++cell; }         // 512 = 51*10 + 2
        }
    } else {
        for (int i = tid; i < cib * 10; i += TPB) {
            int cell = i / 10;
            int r = i - cell * 10;
            float obj = s_obj[cell];
            float2 t = make_float2(0.f, 0.f);
            if (obj > 0.0f) t = tcls2[i];
            float2 v = *reinterpret_cast<const float2*>(&s_pred[cell * 30 + 10 + 2 * r]);
            float dx = v.x - t.x, dy = v.y - t.y;
            acc_cls += obj * (dx * dx + dy * dy);
        }
    }

    // ---- Phase B: per-cell noobj squares + IoU/reg/conf from SMEM ----
    float acc_reg = 0.0f, acc_conf = 0.0f, acc_nobjcnt = 0.0f, acc_noobj = 0.0f;
    if (tid < cib) {
        float obj = o_mine;
        acc_nobjcnt = obj;

        const float* bb = &s_pred[tid * 30];
        float b1x = bb[0], b1y = bb[1], b1w = bb[2], b1h = bb[3], b1c = bb[4];
        float b2x = bb[5], b2y = bb[6], b2w = bb[7], b2h = bb[8], b2c = bb[9];

        float sq = b1x * b1x + b1y * b1y + b1w * b1w + b1h * b1h + b1c * b1c
                 + b2x * b2x + b2y * b2y + b2w * b2w + b2h * b2h + b2c * b2c;
        acc_noobj = (1.0f - obj) * sq;

        if (obj > 0.0f) {
            const float invS = 1.0f / 14.0f;
            float tcx = tb.x * invS, tcy = tb.y * invS;
            float tx1 = tcx - 0.5f * tb.z, ty1 = tcy - 0.5f * tb.w;
            float tx2 = tcx + 0.5f * tb.z, ty2 = tcy + 0.5f * tb.w;
            float tarea = (tx2 - tx1) * (ty2 - ty1);

            float iou1 = iou_pred_vs_tgt(b1x, b1y, b1w, b1h, tx1, ty1, tx2, ty2, tarea);
            float iou2 = iou_pred_vs_tgt(b2x, b2y, b2w, b2h, tx1, ty1, tx2, ty2, tarea);

            bool take1 = (iou1 >= iou2);
            float bx = take1 ? b1x : b2x;
            float by = take1 ? b1y : b2y;
            float bw = take1 ? b1w : b2w;
            float bh = take1 ? b1h : b2h;
            float bc = take1 ? b1c : b2c;
            float biou = take1 ? iou1 : iou2;

            float dx = bx - tb.x;
            float dy = by - tb.y;
            float dw = sqrtf(bw) - sqrtf(tb.z);
            float dh = sqrtf(bh) - sqrtf(tb.w);
            acc_reg = dx * dx + dy * dy + dw * dw + dh * dh;

            float dc = bc - biou;
            acc_conf = dc * dc;
        }
    }

    // ---- Block reduction of 5 accumulators -> SoA partials ----
    float vals[5] = {acc_nobjcnt, acc_reg, acc_conf, acc_noobj, acc_cls};
    #pragma unroll
    for (int k = 0; k < 5; k++) {
        float v = vals[k];
        #pragma unroll
        for (int off = 16; off > 0; off >>= 1)
            v += __shfl_down_sync(0xffffffffu, v, off);
        if (lane == 0) s_red[k * (TPB / 32) + warp] = v;
    }
    __syncthreads();
    if (tid < 5) {
        float v = 0.0f;
        #pragma unroll
        for (int w2 = 0; w2 < TPB / 32; w2++)
            v += s_red[tid * (TPB / 32) + w2];
        g_partials[tid * grid + bid] = v;
    }

    // ---- Last-block finalize ----
    if (tid == 0) {
        __threadfence();
        unsigned int old = atomicInc(&g_counter, (unsigned int)(grid - 1));
        s_last = (old == (unsigned int)(grid - 1)) ? 1 : 0;
    }
    __syncthreads();
    if (!s_last) return;
    __threadfence();   // acquire: order partial reads after the counter observation

    double acc[5] = {0.0, 0.0, 0.0, 0.0, 0.0};
    for (int i = tid; i < grid; i += TPB) {
        #pragma unroll
        for (int k = 0; k < 5; k++)
            acc[k] += (double)g_partials[k * grid + i];
    }
    #pragma unroll
    for (int k = 0; k < 5; k++) {
        double v = acc[k];
        #pragma unroll
        for (int off = 16; off > 0; off >>= 1)
            v += __shfl_down_sync(0xffffffffu, v, off);
        if (lane == 0) s_dred[warp] = v;
        __syncthreads();
        if (tid == 0) {
            double tsum = 0.0;
            #pragma unroll
            for (int w2 = 0; w2 < TPB / 32; w2++) tsum += s_dred[w2];
            s_tot[k] = tsum;
        }
        __syncthreads();
    }

    if (tid == 0) {
        double n_obj   = s_tot[0];
        double n_noobj = (double)n_cells - n_obj;
        double reg_loss   = 5.0 * s_tot[1] / n_obj;
        double conf_loss  = s_tot[2] / n_obj;
        double noobj_loss = 0.5 * s_tot[3] / n_noobj;
        double cls_loss   = s_tot[4] / (double)n_batch;
        double total = reg_loss + conf_loss + noobj_loss + cls_loss;
        out[0] = (float)total;
        out[1] = (float)reg_loss;
        out[2] = (float)conf_loss;
        out[3] = (float)noobj_loss;
        out[4] = (float)cls_loss;
    }
}

extern "C" void kernel_launch(void* const* d_in, const int* in_sizes, int n_in,
                              void* d_out, int out_size)
{
    const float* pred = (const float*)d_in[0];
    const float* tbox = (const float*)d_in[1];
    const float* tcls = (const float*)d_in[2];
    const void*  objmap = d_in[3];
    float* out = (float*)d_out;

    const int n_cells = in_sizes[3];                  // N * S * S
    const int n_batch = in_sizes[0] / (14 * 14 * 30);
    int grid = (n_cells + CPB - 1) / CPB;
    if (grid > MAX_GRID) grid = MAX_GRID;             // not reachable at this shape

    yolo_fused_kernel<<<grid, TPB>>>(pred, tbox, tcls, objmap,
                                     n_cells, (float)n_batch, out);
}